// round 10
// baseline (speedup 1.0000x reference)
#include <cuda_runtime.h>
#include <cuda_fp16.h>

#define HH 512
#define WW 512
#define HW (HH * WW)
#define NC 19
#define NB 8
#define OHH 502
#define OWW 502

#define TOX 64
#define TOY 32
#define INX 74
#define INY 42
#define NT 256
#define NPIX (INY * INX)          // 3108
#define NSWEEP 13                 // ceil(3108/256)
#define ASTR 75                   // stage stride (half2): conflict-free
#define HSTR 67                   // h stride (half2): conflict-free both ways
#define RSTR 80                   // raw stride in halves (160B rows, 16B-aligned)
#define NCG 4                     // class groups per batch
#define CGRP 5                    // max classes per group

#define LSE_N (NB * HW)

// smem byte offsets
#define SMB_A   0                 // 42*75*4 = 12600
#define SMB_B   12600             // 12600
#define SMB_HA  25200             // 42*67*4 = 11256
#define SMB_HB  36456             // 11256
#define SMB_RAW 47712             // 42*80*2 = 6720 (16B aligned)
#define SMB_TGT 54432             // 3108 -> pad 3112
#define SMEM_SZ 57544

__device__ __half g_prob[(size_t)NB * NC * HW];
__device__ unsigned char g_tgt[LSE_N];
__device__ float g_acc[NB * NC];
__device__ int g_is64;

__device__ __forceinline__ float ex2f_(float x) { float y; asm("ex2.approx.ftz.f32 %0, %1;" : "=f"(y) : "f"(x)); return y; }
__device__ __forceinline__ float lg2f_(float x) { float y; asm("lg2.approx.f32 %0, %1;" : "=f"(y) : "f"(x)); return y; }
__device__ __forceinline__ __half2 h2_(unsigned int u) { return *reinterpret_cast<__half2*>(&u); }
__device__ __forceinline__ void cp16_(unsigned int d, const void* s) {
    asm volatile("cp.async.ca.shared.global [%0], [%1], 16;" :: "r"(d), "l"(s));
}
__device__ __forceinline__ void cp4_(unsigned int d, const void* s) {
    asm volatile("cp.async.ca.shared.global [%0], [%1], 4;" :: "r"(d), "l"(s));
}
__device__ __forceinline__ void cp_commit_() { asm volatile("cp.async.commit_group;"); }
__device__ __forceinline__ void cp_wait_() { asm volatile("cp.async.wait_group 0;" ::: "memory"); }

#define L2E 1.4426950408889634f

// ---------------------------------------------------------------------------
// Pass 0: detect int64 vs int32 target (reads only first 4KB)
// ---------------------------------------------------------------------------
__global__ void k_detect(const int* __restrict__ t)
{
    __shared__ int any_nz;
    if (threadIdx.x == 0) any_nz = 0;
    __syncthreads();
    int w = 2 * threadIdx.x + 1;
    int nz = 0;
#pragma unroll
    for (int r = 0; r < 4; r++) nz |= t[w + r * 512];
    if (nz) atomicOr(&any_nz, 1);
    __syncthreads();
    if (threadIdx.x == 0) g_is64 = any_nz ? 0 : 1;
    if (threadIdx.x < NB * NC) g_acc[threadIdx.x] = 0.0f;
}

// ---------------------------------------------------------------------------
// Pass 1: per-pixel softmax -> fp16 probs, target -> u8
// ---------------------------------------------------------------------------
__global__ __launch_bounds__(NT) void k_softmax(const float* __restrict__ pred,
                                                const void* __restrict__ tgt)
{
    int idx = blockIdx.x * NT + threadIdx.x;
    if (idx >= LSE_N) return;
    int b = idx / HW;
    int hw = idx - b * HW;
    const float* p = pred + (size_t)b * NC * HW + hw;
    float v[NC];
    float m = -1e30f;
#pragma unroll
    for (int c = 0; c < NC; c++) { v[c] = p[(size_t)c * HW]; m = fmaxf(m, v[c]); }
    float s = 0.0f;
#pragma unroll
    for (int c = 0; c < NC; c++) s += ex2f_((v[c] - m) * L2E);
    float L = fmaf(m, L2E, lg2f_(s));
    __half* q = g_prob + (size_t)b * NC * HW + hw;
#pragma unroll
    for (int c = 0; c < NC; c++)
        q[(size_t)c * HW] = __float2half(ex2f_(fmaf(v[c], L2E, -L)));

    int lab;
    if (g_is64) lab = ((const int*)tgt)[2 * idx];   // low word of LE int64
    else        lab = ((const int*)tgt)[idx];
    g_tgt[idx] = (unsigned char)lab;
}

// ---------------------------------------------------------------------------
// cp.async copy of one class plane tile into s_raw (clamped-source at edges)
// ---------------------------------------------------------------------------
__device__ __forceinline__ void fetch_plane(const unsigned short* plane,
                                            unsigned int raw_base,
                                            int tid, int y0, int x0)
{
    for (int t = tid; t < INY * 10; t += NT) {
        int r = t / 10;
        int ch = t - r * 10;
        int gy = y0 + r;
        if (gy < HH) {
            int hofs = ch * 8;
            unsigned int dst = raw_base + (unsigned)(r * RSTR + hofs) * 2u;
            if (ch < 9) {
                int gx = x0 + hofs;
                if (gx > WW - 8) gx = WW - 8;
                cp16_(dst, plane + gy * WW + gx);
            } else {
                int gx = x0 + 72;
                if (gx > WW - 2) gx = WW - 2;
                cp4_(dst, plane + gy * WW + gx);
            }
        }
    }
    cp_commit_();
}

// ---------------------------------------------------------------------------
// Pass 2: half2-packed separable 11x11 convs + SSIM. Class-group blocks
// (z = batch*NCG + group) shrink the wave-quantization grain.
// a = (p, p^2) -> (mu1, conv(p^2));  b = (p*t, t) -> (conv(pt), mu2)
// ---------------------------------------------------------------------------
__global__ __launch_bounds__(NT, 4) void k_ssim()
{
    extern __shared__ char smem[];
    __half2* s_a = (__half2*)(smem + SMB_A);
    __half2* s_b = (__half2*)(smem + SMB_B);
    __half2* s_ha = (__half2*)(smem + SMB_HA);
    __half2* s_hb = (__half2*)(smem + SMB_HB);
    unsigned short* s_raw = (unsigned short*)(smem + SMB_RAW);
    unsigned char* s_tgt = (unsigned char*)(smem + SMB_TGT);

    const int tid = threadIdx.x;
    const int zb = blockIdx.z;
    const int b = zb >> 2;                    // batch
    const int c0 = (zb & 3) * CGRP;           // first class of group
    const int ncls = (c0 + CGRP <= NC) ? CGRP : (NC - c0);
    const int y0 = blockIdx.y * TOY;
    const int x0 = blockIdx.x * TOX;
    const int lane = tid & 31;

    const unsigned short* plane0 =
        (const unsigned short*)(g_prob + (size_t)(b * NC) * HW);
    const unsigned int raw_base =
        (unsigned int)__cvta_generic_to_shared(smem + SMB_RAW);

    // prefetch first class of the group
    fetch_plane(plane0 + (size_t)c0 * HW, raw_base, tid, y0, x0);

    // stage target tile once per block
    for (int i = tid; i < NPIX; i += NT) {
        int r = i / INX, cx = i - r * INX;
        int gy = y0 + r, gx = x0 + cx;
        bool ok = (gy < HH) && (gx < WW);
        s_tgt[i] = ok ? g_tgt[b * HW + gy * WW + gx] : (unsigned char)255;
    }

    const float Wt[11] = {0.00102838f, 0.00759876f, 0.03600078f, 0.10936074f,
                          0.21300555f, 0.26601174f, 0.21300555f, 0.10936074f,
                          0.03600078f, 0.00759876f, 0.00102838f};
    __half2 w2[11];
#pragma unroll
    for (int j = 0; j < 11; j++) w2[j] = __float2half2_rn(Wt[j]);

    // horizontal task (constant per thread): row hr, col group hu0 = 11*g
    const int hg = tid / INY;            // 0..6 (only 0..5 valid)
    const int hr = tid - hg * INY;       // 0..41
    const bool hvalid = (hg < 6);
    const int hu0 = hg * 11;

    for (int ci = 0; ci < ncls; ci++) {
        const int c = c0 + ci;
        cp_wait_();
        __syncthreads();   // raw ready; prior-class s_a/s_h reads done

        // stage packed fields from s_raw
#pragma unroll
        for (int it = 0; it < NSWEEP; it++) {
            int i = tid + it * NT;
            if (i < NPIX) {
                int r = i / INX, cx = i - r * INX;
                bool ok = (y0 + r < HH) && (x0 + cx < WW);
                unsigned int pr = ok ? (unsigned int)s_raw[r * RSTR + cx] : 0u;
                unsigned int pp_u = pr * 0x00010001u;            // (p, p)
                unsigned int op_u = 0x00003C00u | (pr << 16);    // (1, p)
                __half2 a = __hmul2(h2_(pp_u), h2_(op_u));       // (p, p^2)
                bool m = (s_tgt[i] == (unsigned char)c);
                unsigned int bv = pr | 0x3C000000u;              // (p, 1)
                int o = r * ASTR + cx;
                s_a[o] = a;
                s_b[o] = h2_(m ? bv : 0u);
            }
        }
        __syncthreads();   // s_a/s_b ready; s_raw consumed

        // async prefetch next class in the group (overlaps horizontal+vertical)
        if (ci + 1 < ncls)
            fetch_plane(plane0 + (size_t)(c + 1) * HW, raw_base, tid, y0, x0);

        // horizontal: 252 tasks, 11 outputs each, balanced
        if (hvalid) {
            const __half2* arow = s_a + hr * ASTR + hu0;
            const __half2* brow = s_b + hr * ASTR + hu0;
            __half2 aa[11], ab[11];
#pragma unroll
            for (int u = 0; u < 11; u++) { aa[u] = h2_(0u); ab[u] = h2_(0u); }
#pragma unroll
            for (int k = 0; k < 21; k++) {
                __half2 av = arow[k];
                __half2 bv = brow[k];
#pragma unroll
                for (int u = 0; u < 11; u++) {
                    int j = k - u;
                    if (j >= 0 && j < 11) {
                        aa[u] = __hfma2(w2[j], av, aa[u]);
                        ab[u] = __hfma2(w2[j], bv, ab[u]);
                    }
                }
            }
            int o = hr * HSTR + hu0;
#pragma unroll
            for (int u = 0; u < 11; u++) {
                if (hu0 + u < TOX) {
                    s_ha[o + u] = aa[u];
                    s_hb[o + u] = ab[u];
                }
            }
        }
        __syncthreads();

        // vertical + SSIM (lanes consecutive u -> conflict-free)
        float vacc = 0.0f;
        {
            const int u = tid & 63;
            const int v0 = (tid >> 6) * 8;
            __half2 aa[8], ab[8];
#pragma unroll
            for (int v = 0; v < 8; v++) { aa[v] = h2_(0u); ab[v] = h2_(0u); }
#pragma unroll
            for (int k = 0; k < 18; k++) {
                int row = (v0 + k) * HSTR + u;
                __half2 ha = s_ha[row];
                __half2 hb = s_hb[row];
#pragma unroll
                for (int v = 0; v < 8; v++) {
                    int j = k - v;
                    if (j >= 0 && j < 11) {
                        aa[v] = __hfma2(w2[j], ha, aa[v]);
                        ab[v] = __hfma2(w2[j], hb, ab[v]);
                    }
                }
            }
            int ox = x0 + u;
            if (ox < OWW) {
#pragma unroll
                for (int v = 0; v < 8; v++) {
                    int oy = y0 + v0 + v;
                    if (oy < OHH) {
                        float2 fa = __half22float2(aa[v]);
                        float2 fb = __half22float2(ab[v]);
                        float mu1 = fa.x, s11 = fa.y, s12 = fb.x, mu2 = fb.y;
                        float mu12 = mu1 * mu2;
                        float m1q = mu1 * mu1, m2q = mu2 * mu2;
                        float var1 = s11 - m1q;
                        float var2 = mu2 - m2q;     // conv(t^2) == conv(t)
                        float cov = s12 - mu12;
                        float num = (2.0f * mu12 + 1e-4f) * (2.0f * cov + 9e-4f);
                        float den = (m1q + m2q + 1e-4f) * (var1 + var2 + 9e-4f);
                        vacc += __fdividef(num, den);
                    }
                }
            }
        }
#pragma unroll
        for (int off = 16; off > 0; off >>= 1) vacc += __shfl_xor_sync(0xffffffffu, vacc, off);
        if (lane == 0) atomicAdd(&g_acc[b * NC + c], vacc);
    }
}

// ---------------------------------------------------------------------------
// Pass 3: per-(b,c) mean -> relu -> 1 - mean
// ---------------------------------------------------------------------------
__global__ __launch_bounds__(256) void k_final(float* __restrict__ out)
{
    int tid = threadIdx.x;
    __shared__ float sr[8];
    float v = 0.0f;
    if (tid < NB * NC) {
        float a = g_acc[tid] * (1.0f / 252004.0f);
        v = a > 0.0f ? a : 0.0f;
    }
#pragma unroll
    for (int off = 16; off > 0; off >>= 1) v += __shfl_xor_sync(0xffffffffu, v, off);
    if ((tid & 31) == 0) sr[tid >> 5] = v;
    __syncthreads();
    if (tid == 0) {
        float s = 0.0f;
#pragma unroll
        for (int i = 0; i < 8; i++) s += sr[i];
        out[0] = 1.0f - s * (1.0f / 152.0f);
    }
}

// ---------------------------------------------------------------------------
extern "C" void kernel_launch(void* const* d_in, const int* in_sizes, int n_in,
                              void* d_out, int out_size)
{
    const float* pred;
    const void* tgt;
    const int PRED_N = NB * NC * HH * WW;
    if (n_in >= 2 && in_sizes[1] == PRED_N) {
        pred = (const float*)d_in[1];
        tgt = d_in[0];
    } else {
        pred = (const float*)d_in[0];
        tgt = (n_in >= 2) ? d_in[1] : d_in[0];
    }

    cudaFuncSetAttribute(k_ssim, cudaFuncAttributeMaxDynamicSharedMemorySize, SMEM_SZ);

    k_detect<<<1, 512>>>((const int*)tgt);
    k_softmax<<<(LSE_N + NT - 1) / NT, NT>>>(pred, tgt);

    dim3 grid((OWW + TOX - 1) / TOX, (OHH + TOY - 1) / TOY, NB * NCG);
    k_ssim<<<grid, NT, SMEM_SZ>>>();

    k_final<<<1, 256>>>((float*)d_out);
}

// round 11
// speedup vs baseline: 1.0317x; 1.0317x over previous
#include <cuda_runtime.h>
#include <cuda_fp16.h>

#define HH 512
#define WW 512
#define HW (HH * WW)
#define NC 19
#define NB 8
#define OHH 502
#define OWW 502

#define TOX 64
#define TOY 32
#define INX 74
#define INY 42
#define NT 256
#define NPIX (INY * INX)          // 3108
#define RSTR 80                   // raw stride in halves (160B rows, 16B-aligned)
#define HSTR2 66                  // s_h stride in ULL (8B) units

#define LSE_N (NB * HW)

typedef unsigned long long ULL;

// smem byte offsets
#define SMB_H   0                 // 42*66*8 = 22176 (interleaved ha/hb)
#define SMB_RAW 22176             // 42*80*2 = 6720 (16B aligned)
#define SMB_TGT 28896             // 3108 -> pad 3112
#define SMEM_SZ 32008

__device__ __half g_prob[(size_t)NB * NC * HW];
__device__ unsigned char g_tgt[LSE_N];
__device__ float g_acc[NB * NC];
__device__ int g_is64;

__device__ __forceinline__ float ex2f_(float x) { float y; asm("ex2.approx.ftz.f32 %0, %1;" : "=f"(y) : "f"(x)); return y; }
__device__ __forceinline__ float lg2f_(float x) { float y; asm("lg2.approx.f32 %0, %1;" : "=f"(y) : "f"(x)); return y; }
__device__ __forceinline__ __half2 h2_(unsigned int u) { return *reinterpret_cast<__half2*>(&u); }
__device__ __forceinline__ unsigned int u2_(__half2 h) { return *reinterpret_cast<unsigned int*>(&h); }
__device__ __forceinline__ void cp16_(unsigned int d, const void* s) {
    asm volatile("cp.async.ca.shared.global [%0], [%1], 16;" :: "r"(d), "l"(s));
}
__device__ __forceinline__ void cp4_(unsigned int d, const void* s) {
    asm volatile("cp.async.ca.shared.global [%0], [%1], 4;" :: "r"(d), "l"(s));
}
__device__ __forceinline__ void cp_commit_() { asm volatile("cp.async.commit_group;"); }
__device__ __forceinline__ void cp_wait_() { asm volatile("cp.async.wait_group 0;" ::: "memory"); }

#define L2E 1.4426950408889634f

// ---------------------------------------------------------------------------
// Pass 0: detect int64 vs int32 target (reads only first 4KB)
// ---------------------------------------------------------------------------
__global__ void k_detect(const int* __restrict__ t)
{
    __shared__ int any_nz;
    if (threadIdx.x == 0) any_nz = 0;
    __syncthreads();
    int w = 2 * threadIdx.x + 1;
    int nz = 0;
#pragma unroll
    for (int r = 0; r < 4; r++) nz |= t[w + r * 512];
    if (nz) atomicOr(&any_nz, 1);
    __syncthreads();
    if (threadIdx.x == 0) g_is64 = any_nz ? 0 : 1;
    if (threadIdx.x < NB * NC) g_acc[threadIdx.x] = 0.0f;
}

// ---------------------------------------------------------------------------
// Pass 1: per-pixel softmax -> fp16 probs, target -> u8
// ---------------------------------------------------------------------------
__global__ __launch_bounds__(NT) void k_softmax(const float* __restrict__ pred,
                                                const void* __restrict__ tgt)
{
    int idx = blockIdx.x * NT + threadIdx.x;
    if (idx >= LSE_N) return;
    int b = idx / HW;
    int hw = idx - b * HW;
    const float* p = pred + (size_t)b * NC * HW + hw;
    float v[NC];
    float m = -1e30f;
#pragma unroll
    for (int c = 0; c < NC; c++) { v[c] = p[(size_t)c * HW]; m = fmaxf(m, v[c]); }
    float s = 0.0f;
#pragma unroll
    for (int c = 0; c < NC; c++) s += ex2f_((v[c] - m) * L2E);
    float L = fmaf(m, L2E, lg2f_(s));
    __half* q = g_prob + (size_t)b * NC * HW + hw;
#pragma unroll
    for (int c = 0; c < NC; c++)
        q[(size_t)c * HW] = __float2half(ex2f_(fmaf(v[c], L2E, -L)));

    int lab;
    if (g_is64) lab = ((const int*)tgt)[2 * idx];   // low word of LE int64
    else        lab = ((const int*)tgt)[idx];
    g_tgt[idx] = (unsigned char)lab;
}

// ---------------------------------------------------------------------------
// cp.async copy of one class plane tile into s_raw (clamped-source at edges;
// garbage only feeds discarded outputs, so no masking needed)
// ---------------------------------------------------------------------------
__device__ __forceinline__ void fetch_plane(const unsigned short* plane,
                                            unsigned int raw_base,
                                            int tid, int y0, int x0)
{
    for (int t = tid; t < INY * 10; t += NT) {
        int r = t / 10;
        int ch = t - r * 10;
        int gy = y0 + r;
        if (gy < HH) {
            int hofs = ch * 8;
            unsigned int dst = raw_base + (unsigned)(r * RSTR + hofs) * 2u;
            if (ch < 9) {
                int gx = x0 + hofs;
                if (gx > WW - 8) gx = WW - 8;
                cp16_(dst, plane + gy * WW + gx);
            } else {
                int gx = x0 + 72;
                if (gx > WW - 2) gx = WW - 2;
                cp4_(dst, plane + gy * WW + gx);
            }
        }
    }
    cp_commit_();
}

// ---------------------------------------------------------------------------
// Pass 2: fused pack+horizontal conv from raw u16 + tgt u8, interleaved h
// storage (ULL = (ha, hb)), vertical conv + SSIM. 2 barriers/class.
// a = (p, p^2) -> (mu1, conv(p^2));  b = (p*t, t) -> (conv(pt), mu2)
// ---------------------------------------------------------------------------
__global__ __launch_bounds__(NT, 4) void k_ssim()
{
    extern __shared__ char smem[];
    ULL* s_h = (ULL*)(smem + SMB_H);
    unsigned short* s_raw = (unsigned short*)(smem + SMB_RAW);
    unsigned char* s_tgt = (unsigned char*)(smem + SMB_TGT);

    const int tid = threadIdx.x;
    const int b = blockIdx.z;
    const int y0 = blockIdx.y * TOY;
    const int x0 = blockIdx.x * TOX;
    const int lane = tid & 31;

    const unsigned short* plane0 =
        (const unsigned short*)(g_prob + (size_t)(b * NC) * HW);
    const unsigned int raw_base =
        (unsigned int)__cvta_generic_to_shared(smem + SMB_RAW);

    // prefetch class 0
    fetch_plane(plane0, raw_base, tid, y0, x0);

    // stage target tile once per block
    for (int i = tid; i < NPIX; i += NT) {
        int r = i / INX, cx = i - r * INX;
        int gy = y0 + r, gx = x0 + cx;
        bool ok = (gy < HH) && (gx < WW);
        s_tgt[i] = ok ? g_tgt[b * HW + gy * WW + gx] : (unsigned char)255;
    }

    const float Wt[11] = {0.00102838f, 0.00759876f, 0.03600078f, 0.10936074f,
                          0.21300555f, 0.26601174f, 0.21300555f, 0.10936074f,
                          0.03600078f, 0.00759876f, 0.00102838f};
    __half2 w2[11];
#pragma unroll
    for (int j = 0; j < 11; j++) w2[j] = __float2half2_rn(Wt[j]);

    // horizontal task (constant per thread): row hr, 11-col group hu0
    const int hg = tid / INY;            // 0..6 (only 0..5 valid)
    const int hr = tid - hg * INY;       // 0..41
    const bool hvalid = (hg < 6);
    const int hu0 = hg * 11;

    for (int c = 0; c < NC; c++) {
        cp_wait_();
        __syncthreads();   // raw(c) ready; vertical(c-1) s_h reads done

        // fused pack + horizontal conv (reads raw u16 + tgt u8 directly)
        if (hvalid) {
            const unsigned short* prow = s_raw + hr * RSTR + hu0;
            const unsigned char* trow = s_tgt + hr * INX + hu0;
            __half2 aa[11], ab[11];
#pragma unroll
            for (int u = 0; u < 11; u++) { aa[u] = h2_(0u); ab[u] = h2_(0u); }
#pragma unroll
            for (int k = 0; k < 21; k++) {
                unsigned int pr = (unsigned int)prow[k];
                unsigned int pp_u = pr * 0x00010001u;            // (p, p)
                unsigned int op_u = 0x00003C00u | (pr << 16);    // (1, p)
                __half2 av = __hmul2(h2_(pp_u), h2_(op_u));      // (p, p^2)
                bool m = (trow[k] == (unsigned char)c);
                __half2 bv = h2_(m ? (pr | 0x3C000000u) : 0u);   // (pt, t)
#pragma unroll
                for (int u = 0; u < 11; u++) {
                    int j = k - u;
                    if (j >= 0 && j < 11) {
                        aa[u] = __hfma2(w2[j], av, aa[u]);
                        ab[u] = __hfma2(w2[j], bv, ab[u]);
                    }
                }
            }
            int o = hr * HSTR2 + hu0;
#pragma unroll
            for (int u = 0; u < 11; u++) {
                if (hu0 + u < TOX) {
                    ULL pk;
                    asm("mov.b64 %0, {%1, %2};" : "=l"(pk)
                        : "r"(u2_(aa[u])), "r"(u2_(ab[u])));
                    s_h[o + u] = pk;
                }
            }
        }
        __syncthreads();   // s_h ready; s_raw consumed

        // async prefetch next class (overlaps vertical)
        if (c + 1 < NC)
            fetch_plane(plane0 + (size_t)(c + 1) * HW, raw_base, tid, y0, x0);

        // vertical + SSIM (LDS.64 interleaved, lanes consecutive u)
        float vacc = 0.0f;
        {
            const int u = tid & 63;
            const int v0 = (tid >> 6) * 8;
            __half2 aa[8], ab[8];
#pragma unroll
            for (int v = 0; v < 8; v++) { aa[v] = h2_(0u); ab[v] = h2_(0u); }
#pragma unroll
            for (int k = 0; k < 18; k++) {
                ULL pk = s_h[(v0 + k) * HSTR2 + u];
                unsigned int lo, hi;
                asm("mov.b64 {%0, %1}, %2;" : "=r"(lo), "=r"(hi) : "l"(pk));
                __half2 ha = h2_(lo), hb = h2_(hi);
#pragma unroll
                for (int v = 0; v < 8; v++) {
                    int j = k - v;
                    if (j >= 0 && j < 11) {
                        aa[v] = __hfma2(w2[j], ha, aa[v]);
                        ab[v] = __hfma2(w2[j], hb, ab[v]);
                    }
                }
            }
            int ox = x0 + u;
            if (ox < OWW) {
#pragma unroll
                for (int v = 0; v < 8; v++) {
                    int oy = y0 + v0 + v;
                    if (oy < OHH) {
                        float2 fa = __half22float2(aa[v]);
                        float2 fb = __half22float2(ab[v]);
                        float mu1 = fa.x, s11 = fa.y, s12 = fb.x, mu2 = fb.y;
                        float mu12 = mu1 * mu2;
                        float m1q = mu1 * mu1, m2q = mu2 * mu2;
                        float var1 = s11 - m1q;
                        float var2 = mu2 - m2q;     // conv(t^2) == conv(t)
                        float cov = s12 - mu12;
                        float num = (2.0f * mu12 + 1e-4f) * (2.0f * cov + 9e-4f);
                        float den = (m1q + m2q + 1e-4f) * (var1 + var2 + 9e-4f);
                        vacc += __fdividef(num, den);
                    }
                }
            }
        }
#pragma unroll
        for (int off = 16; off > 0; off >>= 1) vacc += __shfl_xor_sync(0xffffffffu, vacc, off);
        if (lane == 0) atomicAdd(&g_acc[b * NC + c], vacc);
    }
}

// ---------------------------------------------------------------------------
// Pass 3: per-(b,c) mean -> relu -> 1 - mean
// ---------------------------------------------------------------------------
__global__ __launch_bounds__(256) void k_final(float* __restrict__ out)
{
    int tid = threadIdx.x;
    __shared__ float sr[8];
    float v = 0.0f;
    if (tid < NB * NC) {
        float a = g_acc[tid] * (1.0f / 252004.0f);
        v = a > 0.0f ? a : 0.0f;
    }
#pragma unroll
    for (int off = 16; off > 0; off >>= 1) v += __shfl_xor_sync(0xffffffffu, v, off);
    if ((tid & 31) == 0) sr[tid >> 5] = v;
    __syncthreads();
    if (tid == 0) {
        float s = 0.0f;
#pragma unroll
        for (int i = 0; i < 8; i++) s += sr[i];
        out[0] = 1.0f - s * (1.0f / 152.0f);
    }
}

// ---------------------------------------------------------------------------
extern "C" void kernel_launch(void* const* d_in, const int* in_sizes, int n_in,
                              void* d_out, int out_size)
{
    const float* pred;
    const void* tgt;
    const int PRED_N = NB * NC * HH * WW;
    if (n_in >= 2 && in_sizes[1] == PRED_N) {
        pred = (const float*)d_in[1];
        tgt = d_in[0];
    } else {
        pred = (const float*)d_in[0];
        tgt = (n_in >= 2) ? d_in[1] : d_in[0];
    }

    cudaFuncSetAttribute(k_ssim, cudaFuncAttributeMaxDynamicSharedMemorySize, SMEM_SZ);

    k_detect<<<1, 512>>>((const int*)tgt);
    k_softmax<<<(LSE_N + NT - 1) / NT, NT>>>(pred, tgt);

    dim3 grid((OWW + TOX - 1) / TOX, (OHH + TOY - 1) / TOY, NB);
    k_ssim<<<grid, NT, SMEM_SZ>>>();

    k_final<<<1, 256>>>((float*)d_out);
}